// round 16
// baseline (speedup 1.0000x reference)
#include <cuda_runtime.h>
#include <cstdint>

#define TT 64
#define LL 64
#define BB 16
#define HH 256
#define NDIAG 127
#define GRID 148
#define NTHREADS 512
#define KC 64
#define NCHUNK 8
// 3 stages x 48KB: W float4[16][128] @ +0 (32KB), A float[64][64] @ +32768 (16KB)
#define STAGE_BYTES 49152
#define A_OFF 32768
#define SMEM_TOTAL (3 * STAGE_BYTES)

typedef unsigned long long u64;
typedef uint32_t u32;

// Persistent state (device globals: allocation-free scratch)
__device__ float g_c[LL * BB * HH];              // 4 MB
__device__ float g_h[2][LL * BB * HH];           // 8 MB (double-buffered by parity)
__device__ float g_Wpack[8 * 8 * 16 * 128 * 4];  // 2 MB  [nh][chunk][kquad][col] float4
__device__ unsigned g_bar;

__device__ __forceinline__ float sig_(float v)  { return 1.0f / (1.0f + __expf(-v)); }
__device__ __forceinline__ float tanh_(float v) { return 2.0f / (1.0f + __expf(-2.0f * v)) - 1.0f; }

// Packed fp32x2 FMA (SASS FFMA2)
__device__ __forceinline__ void ffma2(u64 &d, u64 a, u64 b) {
    asm("fma.rn.f32x2 %0, %1, %2, %0;" : "+l"(d) : "l"(a), "l"(b));
}
__device__ __forceinline__ float fold2(u64 p) {
    float2 f = *reinterpret_cast<float2*>(&p);
    return f.x + f.y;
}
__device__ __forceinline__ void cpa16(u32 d, const void* s) {
    asm volatile("cp.async.cg.shared.global [%0], [%1], 16;" :: "r"(d), "l"(s));
}
__device__ __forceinline__ void cpcommit() { asm volatile("cp.async.commit_group;"); }
template<int N> __device__ __forceinline__ void cpwait() {
    asm volatile("cp.async.wait_group %0;" :: "n"(N));
}

__global__ void init_kernel(const float* __restrict__ init_state) {
    int i = blockIdx.x * blockDim.x + threadIdx.x;
    if (i == 0) g_bar = 0u;
    if (i < LL * BB * HH) {
        int l = i / (BB * HH);
        int r = i - l * (BB * HH);
        g_c[i]    = init_state[(l * 2 + 0) * (BB * HH) + r];
        float h   = init_state[(l * 2 + 1) * (BB * HH) + r];
        g_h[0][i] = h;
        g_h[1][i] = h;
    }
}

// Pre-swizzle W: [nh][chunk(8)][kquad(16)][col(128)] float4 = 4 consecutive k of col.
__global__ void prep_kernel(const float* __restrict__ W) {
    int idx = blockIdx.x * blockDim.x + threadIdx.x;   // float4 index
    if (idx >= 8 * 8 * 16 * 128) return;
    int col = idx & 127;           // g*32 + hc
    int p   = (idx >> 7) & 15;     // k-quad
    int c   = (idx >> 11) & 7;
    int nh  = idx >> 14;
    int k   = c * KC + p * 4;
    int gcol = (col >> 5) * 256 + nh * 32 + (col & 31);
    float4 v;
    v.x = W[(size_t)k * 1024 + gcol];
    v.y = W[(size_t)(k + 1) * 1024 + gcol];
    v.z = W[(size_t)(k + 2) * 1024 + gcol];
    v.w = W[(size_t)(k + 3) * 1024 + gcol];
    reinterpret_cast<float4*>(g_Wpack)[idx] = v;
}

// Stage one W chunk (32KB) into stage s: 64B per thread = 4 cp.async.
__device__ __forceinline__ void issueW(u32 sbase, int nh, int c, int s, int tid) {
    const float* wsrc = g_Wpack + ((size_t)(nh * 8 + c) << 13) + tid * 16;
    u32 dst = sbase + s * STAGE_BYTES + (u32)tid * 64;
    cpa16(dst, wsrc);
    cpa16(dst + 16, wsrc + 4);
    cpa16(dst + 32, wsrc + 8);
    cpa16(dst + 48, wsrc + 12);
}

// Per-tile body. 16 warps split as NRG row-groups x NKS k-segments.
// NKS=4 (CG<=2): each warp reads only 1/4 of W.  NKS=2 (CG>=3): reg-bounded.
template<int CG, int NKS>
__device__ __forceinline__ void tile_body(
    char* smem, const float* __restrict__ x,
    const float* __restrict__ bias, float* __restrict__ out,
    const float* __restrict__ hin, float* __restrict__ hout,
    int d, int l_lo, int l_hi, int tile)
{
    constexpr int NRG = 16 / NKS;           // row-groups
    constexpr int RWX = 16 * CG / NRG;      // rows per warp
    constexpr int KQ  = 32 / NKS;           // k2 per segment
    constexpr int NQ  = KQ / 2;             // k-quads per segment
    constexpr int SEG = 16 * CG * 128;      // xch floats per partial set
    const int tid = threadIdx.x;
    const int w   = tid >> 5;
    const int hc  = tid & 31;
    const int nh      = tile & 7;
    const int nh0     = nh << 5;
    const int l_base  = l_lo + (tile >> 3) * CG;

    // --- A source pointers (1 row per thread, clamped so always valid) ---
    const int s_row = tid >> 3;
    const int p8    = (tid & 7) << 3;     // float offset within row
    const int ci_s  = s_row >> 4;
    const int bb_s  = s_row & 15;
    int ls = l_base + ci_s; if (ls > l_hi) ls = l_hi;
    const int ts = d - ls;
    const float* pin = ((ls == 0) ? (x + (bb_s * TT + ts) * HH)
                                  : (hin + ((ls - 1) * BB + bb_s) * HH)) + p8;
    const float* ph  = hin + (ls * BB + bb_s) * HH + p8;

    const u32 sbase = (u32)__cvta_generic_to_shared(smem);
    const u32 a_dst = sbase + A_OFF + (s_row << 8) + ((tid & 7) << 5);

    // --- issue A chunks 0,1 into stages 0,1 (W0,W1 already in flight pre-barrier) ---
    cpa16(a_dst, pin);                    cpa16(a_dst + 16, pin + 4);                    cpcommit();
    cpa16(a_dst + STAGE_BYTES, pin + KC); cpa16(a_dst + STAGE_BYTES + 16, pin + KC + 4); cpcommit();

    u64 acc[RWX][4];
    #pragma unroll
    for (int j = 0; j < RWX; j++)
        #pragma unroll
        for (int g = 0; g < 4; g++) acc[j][g] = 0ull;

    const int rg = w % NRG;
    const int ks = w / NRG;
    const int r0    = rg * RWX;
    const int pbase = ks * NQ;            // k-quad base

    // --- K mainloop: 8 chunks, 3-stage ring, lookahead 2 ---
    #pragma unroll 1
    for (int c = 0; c < NCHUNK; c++) {
        cpwait<1>();
        __syncthreads();                 // chunk c visible; all warps done with c-1
        if (c + 2 < NCHUNK) {
            const int nc = c + 2;
            const int sn = nc % 3;
            issueW(sbase, nh, nc, sn, tid);
            const float* asrc = ((nc & 4) ? ph : pin) + (nc & 3) * KC;
            u32 ad = a_dst + sn * STAGE_BYTES;
            cpa16(ad, asrc); cpa16(ad + 16, asrc + 4);
        }
        cpcommit();
        const int s = c % 3;
        const float* a = (const float*)(smem + s * STAGE_BYTES + A_OFF) + r0 * KC;
        const float4* w4 = (const float4*)(smem + s * STAGE_BYTES) + hc;
        #pragma unroll
        for (int q = 0; q < NQ; q++) {
            const int p = pbase + q;
            ulonglong2 wv[4];
            #pragma unroll
            for (int g = 0; g < 4; g++)
                wv[g] = *reinterpret_cast<const ulonglong2*>(w4 + p * 128 + g * 32);
            #pragma unroll
            for (int j = 0; j < RWX; j++) {
                ulonglong2 ap = *reinterpret_cast<const ulonglong2*>(a + j * KC + (p << 2));
                #pragma unroll
                for (int g = 0; g < 4; g++) {
                    ffma2(acc[j][g], ap.x, wv[g].x);
                    ffma2(acc[j][g], ap.y, wv[g].y);
                }
            }
        }
    }

    // --- combine k-segments (xch overlays stage-2 region; quiescent after c=7) ---
    __syncthreads();
    float* xch = (float*)(smem + 2 * STAGE_BYTES);   // (NKS-1)*SEG floats <= 48KB
    if (ks > 0) {
        float* xs = xch + (ks - 1) * SEG + r0 * 128 + hc;
        #pragma unroll
        for (int j = 0; j < RWX; j++)
            #pragma unroll
            for (int g = 0; g < 4; g++)
                xs[j * 128 + g * 32] = fold2(acc[j][g]);
    }
    __syncthreads();
    if (ks == 0) {
        const int hcol = nh0 + hc;
        const float bi = bias[hcol];
        const float bj = bias[256 + hcol];
        const float bf = bias[512 + hcol];
        const float bo = bias[768 + hcol];
        #pragma unroll
        for (int j = 0; j < RWX; j++) {
            const int row = r0 + j;
            const int ci  = row >> 4;
            const int bb  = row & 15;
            const int l   = l_base + ci;
            if (l <= l_hi) {
                const int t    = d - l;
                const int sidx = (l * BB + bb) * HH + hcol;
                float z[4];
                #pragma unroll
                for (int g = 0; g < 4; g++) z[g] = fold2(acc[j][g]);
                #pragma unroll
                for (int seg = 0; seg < NKS - 1; seg++) {
                    const float* xr = xch + seg * SEG + row * 128 + hc;
                    #pragma unroll
                    for (int g = 0; g < 4; g++) z[g] += xr[g * 32];
                }
                float zi = z[0] + bi;
                float zj = z[1] + bj;
                float zf = z[2] + bf;
                float zo = z[3] + bo;
                float cold = g_c[sidx];
                float ncv  = sig_(zf + 1.0f) * cold + sig_(zi) * tanh_(zj);
                float nhv  = sig_(zo) * tanh_(ncv);
                g_c[sidx]  = ncv;
                hout[sidx] = nhv;
                if (l == LL - 1) out[(bb * TT + t) * HH + hcol] = nhv;
            }
        }
    }
}

__global__ void __launch_bounds__(NTHREADS, 1)
lstm_kernel(const float* __restrict__ x, const float* __restrict__ bias,
            float* __restrict__ out) {
    extern __shared__ __align__(16) char smem[];
    const int tid = threadIdx.x;
    const int G   = gridDim.x;
    const u32 sbase = (u32)__cvta_generic_to_shared(smem);

    // --- prologue: prefetch W chunks 0,1 for d=0 (ntiles=8) ---
    {
        const bool act = (blockIdx.x < 8);
        if (act) issueW(sbase, blockIdx.x & 7, 0, 0, tid);
        cpcommit();
        if (act) issueW(sbase, blockIdx.x & 7, 1, 1, tid);
        cpcommit();
    }

    for (int d = 0; d < NDIAG; d++) {
        const int l_lo = (d - (TT - 1) > 0) ? d - (TT - 1) : 0;
        const int l_hi = (d < LL - 1) ? d : LL - 1;
        const int n    = l_hi - l_lo + 1;
        const int CG   = (n + 17) / 18;          // 1..4 cells per M-tile
        const int ngroups = (n + CG - 1) / CG;
        const int ntiles  = ngroups << 3;        // <= 144
        const float* hin  = g_h[(d + 1) & 1];
        float*       hout = g_h[d & 1];

        if ((int)blockIdx.x < ntiles) {
            const int tile = blockIdx.x;
            if      (CG == 4) tile_body<4, 2>(smem, x, bias, out, hin, hout, d, l_lo, l_hi, tile);
            else if (CG == 3) tile_body<3, 2>(smem, x, bias, out, hin, hout, d, l_lo, l_hi, tile);
            else if (CG == 2) tile_body<2, 4>(smem, x, bias, out, hin, hout, d, l_lo, l_hi, tile);
            else              tile_body<1, 4>(smem, x, bias, out, hin, hout, d, l_lo, l_hi, tile);
        }

        if (d < NDIAG - 1) {
            // --- cross-barrier W prefetch for next diagonal (state-independent) ---
            const int d2    = d + 1;
            const int l_lo2 = (d2 - (TT - 1) > 0) ? d2 - (TT - 1) : 0;
            const int l_hi2 = (d2 < LL - 1) ? d2 : LL - 1;
            const int n2    = l_hi2 - l_lo2 + 1;
            const int CG2   = (n2 + 17) / 18;
            const int ntiles2 = ((n2 + CG2 - 1) / CG2) << 3;
            const bool actN = ((int)blockIdx.x < ntiles2);
            if (actN) issueW(sbase, blockIdx.x & 7, 0, 0, tid);
            cpcommit();
            if (actN) issueW(sbase, blockIdx.x & 7, 1, 1, tid);
            cpcommit();

            // --- grid-wide barrier (release + L1 invalidate via membar.gpu) ---
            __threadfence();
            __syncthreads();
            if (tid == 0) {
                unsigned target = (unsigned)G * (unsigned)(d + 1);
                atomicAdd(&g_bar, 1u);
                while (*((volatile unsigned*)&g_bar) < target) { }
            }
            __syncthreads();
        }
    }
}

extern "C" void kernel_launch(void* const* d_in, const int* in_sizes, int n_in,
                              void* d_out, int out_size) {
    const float* x    = (const float*)d_in[0];   // (B, T, H)
    const float* init = (const float*)d_in[1];   // (L, 2, B, H)
    const float* W    = (const float*)d_in[2];   // (2H, 4H)
    const float* bias = (const float*)d_in[3];   // (4H,)
    float* out        = (float*)d_out;           // (B, T, H)

    cudaFuncSetAttribute(lstm_kernel, cudaFuncAttributeMaxDynamicSharedMemorySize, SMEM_TOTAL);
    init_kernel<<<(LL * BB * HH + 255) / 256, 256>>>(init);
    prep_kernel<<<(8 * 8 * 16 * 128 + 255) / 256, 256>>>(W);
    lstm_kernel<<<GRID, NTHREADS, SMEM_TOTAL>>>(x, bias, out);
}